// round 16
// baseline (speedup 1.0000x reference)
#include <cuda_runtime.h>
#include <cstdint>
#include <math.h>

// NUFFT layer — fully analytic (round-8 math), cluster-of-8 structure.
// Round-15/16: (1) phase A re-tiled 6 mode-chunks x 2 particle-halves -> 4
// sincos/thread (was 8, 12x redundant); (2) warps 12-15 precompute output
// (z, z^12) table pre-barrier; (3) partials distributed via DSMEM
// st.shared::cluster all-to-all -> post-barrier reduce is local LDS (the
// g_part global + __threadfence + __ldcg tail deleted).
// (Round-15 failed to compile: missing <cstdint>. Identical otherwise.)

#define NMODES 48
#define NBATCH 8
#define NPART  1024
#define CLUST  8
#define GRIDB  (NBATCH * CLUST)   // 64
#define TPB    512

#define TWO_PI_F 6.2831853071795864769f

#define CMUL(rr, ri, ar, ai, br, bi) \
    do { rr = fmaf((ar), (br), -(ai) * (bi)); ri = fmaf((ar), (bi), (ai) * (br)); } while (0)
#define CSQ(rr, ri, ar, ai) \
    do { rr = fmaf((ar), (ar), -(ai) * (ai)); ri = 2.f * (ar) * (ai); } while (0)

__device__ __forceinline__ float frac_mx(float m, float x)
{   // frac(m*x) in ~[-0.5,0.5]; exact Dekker split (m <= 40 < 2^7, x fp32)
    float hi = m * x;
    float lo = fmaf(m, x, -hi);
    return (hi - rintf(hi)) + lo;
}

__device__ __forceinline__ void st_cluster_f32(uint32_t laddr, int dst, float val)
{
    uint32_t raddr;
    asm volatile("mapa.shared::cluster.u32 %0, %1, %2;"
                 : "=r"(raddr) : "r"(laddr), "r"(dst));
    asm volatile("st.shared::cluster.f32 [%0], %1;"
                 :: "r"(raddr), "f"(val) : "memory");
}

__global__ __launch_bounds__(TPB, 1) __cluster_dims__(CLUST, 1, 1)
void k_fused(
    const float* __restrict__ x,
    const float* __restrict__ sigma_var,
    const float* __restrict__ shift0,
    const float* __restrict__ shift1,
    const float* __restrict__ amp0,
    const float* __restrict__ amp1,
    float* __restrict__ out)
{
    const int b    = blockIdx.x >> 3;     // batch
    const int rank = blockIdx.x & 7;      // rank within cluster
    const int tid  = threadIdx.x;
    const int w    = tid >> 5;
    const int lane = tid & 31;

    __shared__ float  rowparts[2 * NMODES][16];   // [A|B x mode][rank*2+half]
    __shared__ float4 zs[128];                    // (z, z^12) per local particle
    __shared__ float4 tabU[NMODES];               // (A, B, U0, U1)
    __shared__ float2 tabV[NMODES];               // (V0, V1) with-deconv (edge f)
    __shared__ float  sf0[12], sf1[12];           // edge field values

    if (w < 12) {
        // ---- Phase A: chunk c = w%6 (modes 8c..8c+7), half h = w/6 -------
        const int c = w % 6;
        const int h = w / 6;
        const float m8c = (float)(8 * c);

        float v[16];
#pragma unroll
        for (int k = 0; k < 16; ++k) v[k] = 0.f;

#pragma unroll
        for (int pp = 0; pp < 2; ++pp) {
            const float xv = x[b * NPART + rank * 128 + h * 64 + pp * 32 + lane];
            float zr, zi;                         // z = e^{2*pi*i*x}
            __sincosf(TWO_PI_F * (xv - rintf(xv)), &zi, &zr);
            float cr, ci;                         // base = z^{8c} (exact)
            if (c == 0) { cr = 1.f; ci = 0.f; }
            else        { __sincosf(TWO_PI_F * frac_mx(m8c, xv), &ci, &cr); }
#pragma unroll
            for (int j = 0; j < 8; ++j) {
                v[2 * j]     += cr;
                v[2 * j + 1] += ci;
                float nr = fmaf(cr, zr, -ci * zi);
                float ni = fmaf(ci, zr,  cr * zi);
                cr = nr; ci = ni;
            }
        }
#pragma unroll
        for (int s = 0; s < 4; ++s) {             // 15-shfl halving on v[16]
            const int  half = 8 >> s;
            const bool up   = (lane >> s) & 1;
#pragma unroll
            for (int k = 0; k < half; ++k) {
                float send = up ? v[k] : v[k + half];
                float recv = __shfl_xor_sync(0xffffffffu, send, 1 << s);
                v[k] = (up ? v[k + half] : v[k]) + recv;
            }
        }
        v[0] += __shfl_xor_sync(0xffffffffu, v[0], 16);
        if (lane < 16) {
            const int r   = __brev(lane) >> 28;   // bitrev4 -> accumulator idx
            const int m   = 8 * c + (r >> 1);
            const int row = (r & 1) * NMODES + m;
            uint32_t laddr = (uint32_t)__cvta_generic_to_shared(
                                 &rowparts[row][rank * 2 + h]);
#pragma unroll
            for (int dst = 0; dst < 8; ++dst)
                st_cluster_f32(laddr, dst, v[0]);
        }
    } else {
        // ---- warps 12-15: output z-table (z, z^12) for 128 particles -----
        const int t2 = tid - 384;                 // 0..127
        const float xv = x[b * NPART + rank * 128 + t2];
        float zr, zi;
        __sincosf(TWO_PI_F * (xv - rintf(xv)), &zi, &zr);
        float z2r, z2i, z4r, z4i, z8r, z8i, z12r, z12i;
        CSQ(z2r, z2i, zr,  zi);
        CSQ(z4r, z4i, z2r, z2i);
        CSQ(z8r, z8i, z4r, z4i);
        CMUL(z12r, z12i, z8r, z8i, z4r, z4i);
        zs[t2] = make_float4(zr, zi, z12r, z12i);
    }

    // ---- cluster rendezvous (release/acquire covers cluster smem) --------
    asm volatile("barrier.cluster.arrive.aligned;" ::: "memory");
    asm volatile("barrier.cluster.wait.aligned;"   ::: "memory");

    // ---- spectral multiplier tables (local LDS reduce of 16 partials) ----
    if (tid < NMODES) {
        const int m = tid;
        const float4* pa = (const float4*)rowparts[m];
        const float4* pb = (const float4*)rowparts[NMODES + m];
        float A = 0.f, B = 0.f;
#pragma unroll
        for (int k = 0; k < 4; ++k) {
            float4 ua = pa[k], ub = pb[k];
            A += (ua.x + ua.y) + (ua.z + ua.w);
            B += (ub.x + ub.y) + (ub.z + ub.w);
        }
        const double TWO_PI_D = 6.283185307179586476925286766559;
        const double taud  = 12.0 / ((TWO_PI_D * 2001.0) * (TWO_PI_D * 2001.0));
        const float TAUF     = (float)taud;
        const float SQPIOTAU = (float)sqrt(3.14159265358979323846 / taud);
        const float s_   = sigma_var[0];
        const float q0   = 25.f * shift0[0] * shift0[0];
        const float q1   = 25.f * shift1[0] * shift1[0];
        const float FOURPI = 12.566370614359172f;
        float kk = TWO_PI_F * (float)m;
        float K2 = kk * kk;
        float fold = (m == 0) ? 1.f : 2.f;
        float base0 = fold * (-amp0[0]) * FOURPI / (K2 + q0);
        float inv  = 1.f / (K2 + q1);
        float base1 = fold * amp1[0] * FOURPI * inv * inv;
        float eg = __expf(-0.5f * s_ * s_ * K2);
        float eU = TWO_PI_F * eg;                 // window x deconv = 2*pi exactly
        float eV = SQPIOTAU * __expf((TAUF - 0.5f * s_ * s_) * K2);
        tabU[m] = make_float4(A, B, base0 * eU, base1 * eU);
        tabV[m] = make_float2(base0 * eV, base1 * eV);
    }
    __syncthreads();

    // ---- edge field: 16 slots x 4 threads (WHOLE warps 0,1; 12 used) -----
    if (tid < 64) {
        const int e = tid >> 2;
        const int q = tid & 3;
        const int g = (e < 6) ? e : ((e < 12) ? (1995 + (e - 6)) : 1000);

        const float C_HI = (float)(1.0 / 2001.0);
        const float C_LO = (float)(1.0 / 2001.0 - (double)((float)(1.0 / 2001.0)));
        const float gf     = (float)g;
        const float phi_hi = gf * C_HI;
        const float phi_lo = fmaf(gf, C_HI, -phi_hi) + gf * C_LO;

        float sw_, cw_;
        __sincosf(TWO_PI_F * ((phi_hi - rintf(phi_hi)) + phi_lo), &sw_, &cw_);
        float zr, zi;
        if (q == 0) { zr = 1.f; zi = 0.f; }
        else {
            float m0f = (float)(12 * q);
            float hi2 = m0f * phi_hi;
            float lo2 = fmaf(m0f, phi_hi, -hi2);
            float f   = (hi2 - rintf(hi2)) + (lo2 + m0f * phi_lo);
            __sincosf(TWO_PI_F * (f - rintf(f)), &zi, &zr);
        }
        float acc0 = 0.f, acc1 = 0.f;
#pragma unroll
        for (int j = 0; j < 12; ++j) {
            const int m = 12 * q + j;
            float4 t4 = tabU[m];
            float2 v2 = tabV[m];
            float tt = fmaf(t4.x, zr, t4.y * zi);
            acc0 = fmaf(v2.x, tt, acc0);
            acc1 = fmaf(v2.y, tt, acc1);
            float nzr = fmaf(zr, cw_, -zi * sw_);
            float nzi = fmaf(zi, cw_,  zr * sw_);
            zr = nzr; zi = nzi;
        }
        acc0 += __shfl_xor_sync(0xffffffffu, acc0, 1);
        acc0 += __shfl_xor_sync(0xffffffffu, acc0, 2);
        acc1 += __shfl_xor_sync(0xffffffffu, acc1, 1);
        acc1 += __shfl_xor_sync(0xffffffffu, acc1, 2);
        if (q == 0 && e < 12) { sf0[e] = acc0; sf1[e] = acc1; }
    }
    __syncthreads();

    // ---- output: 4 threads/particle, 12-mode chains, z from smem ---------
    {
        const int s  = tid >> 2;                  // 0..127
        const int q  = tid & 3;
        const int p  = b * NPART + rank * 128 + s;

        float4 st = zs[s];                        // (z, z^12)
        const float zr = st.x, zi = st.y, z12r = st.z, z12i = st.w;
        float z24r, z24i;
        CSQ(z24r, z24i, z12r, z12i);
        float b1r = (q & 1) ? z12r : 1.f, b1i = (q & 1) ? z12i : 0.f;
        float b2r = (q & 2) ? z24r : 1.f, b2i = (q & 2) ? z24i : 0.f;
        float cr, ci;                             // base = z^{12q}
        CMUL(cr, ci, b1r, b1i, b2r, b2i);

        float acc0 = 0.f, acc1 = 0.f;
#pragma unroll
        for (int j = 0; j < 12; ++j) {
            float4 t4 = tabU[12 * q + j];
            float tt = fmaf(t4.x, cr, t4.y * ci);
            acc0 = fmaf(t4.z, tt, acc0);
            acc1 = fmaf(t4.w, tt, acc1);
            float nr = fmaf(cr, zr, -ci * zi);
            float ni = fmaf(ci, zr,  cr * zi);
            cr = nr; ci = ni;
        }
        acc0 += __shfl_xor_sync(0xffffffffu, acc0, 1);
        acc0 += __shfl_xor_sync(0xffffffffu, acc0, 2);
        acc1 += __shfl_xor_sync(0xffffffffu, acc1, 1);
        acc1 += __shfl_xor_sync(0xffffffffu, acc1, 2);

        if (q == 0) {
            const float xv = x[p];
            // wrap corrections (reference clamps; Poisson periodizes)
            const double TWO_PI_D = 6.283185307179586476925286766559;
            const float TAUF    = (float)(12.0 / ((TWO_PI_D * 2001.0) * (TWO_PI_D * 2001.0)));
            const float inv4tau = 1.f / (4.f * TAUF);
            const float invN    = (float)(1.0 / 2001.0);
            const int m0 = __float2int_rn(xv * 2001.0f);
            if (m0 <= 6) {
#pragma unroll
                for (int j = 1; j <= 6; ++j) {    // phantom n = -j -> grid 2001-j
                    float d = xv + (float)j * invN;
                    float wgt = invN * __expf(-d * d * inv4tau);
                    acc0 -= wgt * sf0[12 - j];
                    acc1 -= wgt * sf1[12 - j];
                }
            }
            if (m0 >= 1994) {
#pragma unroll
                for (int j = 0; j <= 5; ++j) {    // phantom n = 2001+j -> grid j
                    float d = xv - 1.f - (float)j * invN;
                    float wgt = invN * __expf(-d * d * inv4tau);
                    acc0 -= wgt * sf0[j];
                    acc1 -= wgt * sf1[j];
                }
            }
            out[2 * p]     = acc0;
            out[2 * p + 1] = acc1;
        }
    }
}

// ---------------------------------------------------------------------------
extern "C" void kernel_launch(void* const* d_in, const int* in_sizes, int n_in,
                              void* d_out, int out_size)
{
    (void)in_sizes; (void)n_in; (void)out_size;
    k_fused<<<GRIDB, TPB>>>((const float*)d_in[0], (const float*)d_in[1],
                            (const float*)d_in[2], (const float*)d_in[3],
                            (const float*)d_in[4], (const float*)d_in[5],
                            (float*)d_out);
}